// round 7
// baseline (speedup 1.0000x reference)
#include <cuda_runtime.h>
#include <math.h>

#define NN   50000
#define NE   800000
#define NF   64
#define NRBF 10
#define NG   512
#define NH   64
#define NTYPE 95

// ---------------- scratch (device globals) ----------------
__device__ float4 g_x4[NN * 16];       // node features
__device__ float4 g_h4[NN * 16];       // pre-message transform
__device__ float4 g_agg4[NN * 16];     // scatter accumulator
__device__ float4 g_gsum4[NG * 16];    // per-graph sums
__device__ float  g_gcnt[NG];          // per-graph counts
__device__ float  g_hemb[NTYPE * NF];  // emb @ W1[0] + b1[0]

// ---------------- helpers ----------------
__device__ __forceinline__ void red_add_v4(float* p, float4 v) {
    asm volatile("red.global.add.v4.f32 [%0], {%1,%2,%3,%4};"
                 :: "l"(p), "f"(v.x), "f"(v.y), "f"(v.z), "f"(v.w) : "memory");
}
__device__ __forceinline__ void red_add_f(float* p, float v) {
    asm volatile("red.global.add.f32 [%0], %1;" :: "l"(p), "f"(v) : "memory");
}
__device__ __forceinline__ unsigned long long pack2(float x, float y) {
    unsigned long long r;
    asm("mov.b64 %0, {%1,%2};" : "=l"(r) : "f"(x), "f"(y));
    return r;
}
__device__ __forceinline__ void fma2(unsigned long long& d, unsigned long long a, unsigned long long b) {
    asm("fma.rn.f32x2 %0, %1, %2, %3;" : "=l"(d) : "l"(a), "l"(b), "l"(d));
}
__device__ __forceinline__ float2 unpack2(unsigned long long v) {
    float2 f;
    asm("mov.b64 {%0,%1}, %2;" : "=f"(f.x), "=f"(f.y) : "l"(v));
    return f;
}
__device__ __forceinline__ float4 f4mul(float4 a, float4 b) {
    return make_float4(a.x * b.x, a.y * b.y, a.z * b.z, a.w * b.w);
}
__device__ __forceinline__ float sp(float x) {   // stable softplus
    return fmaxf(x, 0.0f) + log1pf(expf(-fabsf(x)));
}

// ---------------- tiny GEMM: g_hemb = emb @ W1[0] + b1[0]  (95 x 64) ----------------
__global__ void k_emb_w1(const float* __restrict__ emb, const float* __restrict__ W,
                         const float* __restrict__ b) {
    __shared__ float Ws[NF * NF];
    int t = threadIdx.x;
    for (int i = t; i < NF * NF; i += 64) Ws[i] = W[i];
    __syncthreads();
    int row = blockIdx.x;
    float acc = b[t];
    const float* er = emb + row * NF;
#pragma unroll 8
    for (int k = 0; k < NF; k++) acc += er[k] * Ws[k * NF + t];
    g_hemb[row * NF + t] = acc;
}

// ---------------- conv0 front: x = emb[ids], h = hemb[ids], agg = 0, pool zero ----------------
__global__ void k_embed0(const int* __restrict__ ids, const float4* __restrict__ emb4) {
    int t = blockIdx.x * blockDim.x + threadIdx.x;
    if (t < NG * 16) g_gsum4[t] = make_float4(0.f, 0.f, 0.f, 0.f);
    if (t < NG) g_gcnt[t] = 0.0f;
    if (t >= NN * 16) return;
    int n = t >> 4, c = t & 15;
    int id = ids[n];
    g_x4[t] = emb4[(size_t)id * 16 + c];
    g_h4[t] = ((const float4*)g_hemb)[(size_t)id * 16 + c];
    g_agg4[t] = make_float4(0.f, 0.f, 0.f, 0.f);
}

// ---------------- fused GEMM pair: 64 rows/block, 256 thr, 2 rows x 8 cols/thread ----
// phase 1: x' = softplus(g_x + g_agg @ W2 + b2)  -> g_x (and smem)
// phase 2: g_h = x' @ W1n + b1n ; zero g_agg
__global__ __launch_bounds__(256) void k_gemm_fused(
        const float* __restrict__ W2, const float* __restrict__ b2,
        const float* __restrict__ W1n, const float* __restrict__ b1n) {
    __shared__ float4 Ws4[NF * 16];     // holds W2, then W1n
    __shared__ float4 xs4[64 * 17];     // agg tile, then x' tile
    __shared__ float  bsA[NF], bsB[NF];

    int t = threadIdx.x;
    const float4* W2v = (const float4*)W2;
#pragma unroll
    for (int i = 0; i < 4; i++) Ws4[t + 256 * i] = W2v[t + 256 * i];
    if (t < NF) { bsA[t] = b2[t]; bsB[t] = b1n[t]; }

    int rowbase = blockIdx.x * 64;
#pragma unroll
    for (int i = 0; i < 4; i++) {
        int idx = t + 256 * i;                // [0,1024)
        int lr = idx >> 4, c = idx & 15;
        int row = rowbase + lr;
        if (row < NN) xs4[lr * 17 + c] = g_agg4[(size_t)row * 16 + c];
    }
    __syncthreads();

    int cg = t & 7;              // cols cg*8..cg*8+7
    int rl = t >> 3;             // rows rl, rl+32

    // ---------- phase 1 ----------
    unsigned long long a[2][4];
    {
        int cb = cg * 8;
        unsigned long long b0 = pack2(bsA[cb + 0], bsA[cb + 1]);
        unsigned long long b1v = pack2(bsA[cb + 2], bsA[cb + 3]);
        unsigned long long b2v = pack2(bsA[cb + 4], bsA[cb + 5]);
        unsigned long long b3v = pack2(bsA[cb + 6], bsA[cb + 7]);
#pragma unroll
        for (int i = 0; i < 2; i++) { a[i][0] = b0; a[i][1] = b1v; a[i][2] = b2v; a[i][3] = b3v; }
    }
#pragma unroll 4
    for (int k4 = 0; k4 < 16; k4++) {
        float4 xv[2];
        xv[0] = xs4[rl * 17 + k4];
        xv[1] = xs4[(rl + 32) * 17 + k4];
#pragma unroll
        for (int sub = 0; sub < 4; sub++) {
            int k = k4 * 4 + sub;
            const ulonglong2* wp = (const ulonglong2*)(Ws4 + k * 16 + cg * 2);
            ulonglong2 wA = wp[0], wB = wp[1];
#pragma unroll
            for (int i = 0; i < 2; i++) {
                float xk = (sub == 0) ? xv[i].x : (sub == 1) ? xv[i].y : (sub == 2) ? xv[i].z : xv[i].w;
                unsigned long long s = pack2(xk, xk);
                fma2(a[i][0], s, wA.x);
                fma2(a[i][1], s, wA.y);
                fma2(a[i][2], s, wB.x);
                fma2(a[i][3], s, wB.y);
            }
        }
    }

    float4 res[2][2];
#pragma unroll
    for (int i = 0; i < 2; i++) {
        int row = rowbase + rl + 32 * i;
        if (row >= NN) continue;
        float2 p0 = unpack2(a[i][0]), p1 = unpack2(a[i][1]);
        float2 p2 = unpack2(a[i][2]), p3 = unpack2(a[i][3]);
        size_t o = (size_t)row * 16 + cg * 2;
        float4 x0 = g_x4[o], x1 = g_x4[o + 1];
        res[i][0] = make_float4(sp(x0.x + p0.x), sp(x0.y + p0.y), sp(x0.z + p1.x), sp(x0.w + p1.y));
        res[i][1] = make_float4(sp(x1.x + p2.x), sp(x1.y + p2.y), sp(x1.z + p3.x), sp(x1.w + p3.y));
        g_x4[o]     = res[i][0];
        g_x4[o + 1] = res[i][1];
    }
    __syncthreads();   // everyone done reading agg tile + W2

    // store x' into the tile; reload W with W1n
#pragma unroll
    for (int i = 0; i < 2; i++) {
        xs4[(rl + 32 * i) * 17 + cg * 2]     = res[i][0];
        xs4[(rl + 32 * i) * 17 + cg * 2 + 1] = res[i][1];
    }
    const float4* W1v = (const float4*)W1n;
#pragma unroll
    for (int i = 0; i < 4; i++) Ws4[t + 256 * i] = W1v[t + 256 * i];
    __syncthreads();

    // ---------- phase 2 ----------
    {
        int cb = cg * 8;
        unsigned long long b0 = pack2(bsB[cb + 0], bsB[cb + 1]);
        unsigned long long b1v = pack2(bsB[cb + 2], bsB[cb + 3]);
        unsigned long long b2v = pack2(bsB[cb + 4], bsB[cb + 5]);
        unsigned long long b3v = pack2(bsB[cb + 6], bsB[cb + 7]);
#pragma unroll
        for (int i = 0; i < 2; i++) { a[i][0] = b0; a[i][1] = b1v; a[i][2] = b2v; a[i][3] = b3v; }
    }
#pragma unroll 4
    for (int k4 = 0; k4 < 16; k4++) {
        float4 xv[2];
        xv[0] = xs4[rl * 17 + k4];
        xv[1] = xs4[(rl + 32) * 17 + k4];
#pragma unroll
        for (int sub = 0; sub < 4; sub++) {
            int k = k4 * 4 + sub;
            const ulonglong2* wp = (const ulonglong2*)(Ws4 + k * 16 + cg * 2);
            ulonglong2 wA = wp[0], wB = wp[1];
#pragma unroll
            for (int i = 0; i < 2; i++) {
                float xk = (sub == 0) ? xv[i].x : (sub == 1) ? xv[i].y : (sub == 2) ? xv[i].z : xv[i].w;
                unsigned long long s = pack2(xk, xk);
                fma2(a[i][0], s, wA.x);
                fma2(a[i][1], s, wA.y);
                fma2(a[i][2], s, wB.x);
                fma2(a[i][3], s, wB.y);
            }
        }
    }
#pragma unroll
    for (int i = 0; i < 2; i++) {
        int row = rowbase + rl + 32 * i;
        if (row >= NN) continue;
        float2 p0 = unpack2(a[i][0]), p1 = unpack2(a[i][1]);
        float2 p2 = unpack2(a[i][2]), p3 = unpack2(a[i][3]);
        size_t o = (size_t)row * 16 + cg * 2;
        g_h4[o]     = make_float4(p0.x, p0.y, p1.x, p1.y);
        g_h4[o + 1] = make_float4(p2.x, p2.y, p3.x, p3.y);
        g_agg4[o]     = make_float4(0.f, 0.f, 0.f, 0.f);
        g_agg4[o + 1] = make_float4(0.f, 0.f, 0.f, 0.f);
    }
}

// ---------------- final GEMM + pool: 64 rows/block, 128 thr (proven R6 kernel, mode 2) ----
__global__ __launch_bounds__(128) void k_gemm_final(
        const float* __restrict__ W, const float* __restrict__ b,
        const int* __restrict__ batch) {
    __shared__ float4 Ws4[NF * 16];
    __shared__ float4 xs4[64 * 17];
    __shared__ float  bs[NF];

    int t = threadIdx.x;
    const float4* W4 = (const float4*)W;
#pragma unroll
    for (int i = 0; i < 8; i++) Ws4[t + 128 * i] = W4[t + 128 * i];
    if (t < NF) bs[t] = b[t];

    int rowbase = blockIdx.x * 64;
#pragma unroll
    for (int i = 0; i < 8; i++) {
        int idx = t + 128 * i;
        int lr = idx >> 4, c = idx & 15;
        int row = rowbase + lr;
        if (row < NN) xs4[lr * 17 + c] = g_agg4[(size_t)row * 16 + c];
    }
    __syncthreads();

    int cg = t & 7;
    int rl = t >> 3;

    unsigned long long a[4][4];
    {
        int cb = cg * 8;
        unsigned long long b0 = pack2(bs[cb + 0], bs[cb + 1]);
        unsigned long long b1 = pack2(bs[cb + 2], bs[cb + 3]);
        unsigned long long b2 = pack2(bs[cb + 4], bs[cb + 5]);
        unsigned long long b3 = pack2(bs[cb + 6], bs[cb + 7]);
#pragma unroll
        for (int i = 0; i < 4; i++) { a[i][0] = b0; a[i][1] = b1; a[i][2] = b2; a[i][3] = b3; }
    }

#pragma unroll 4
    for (int k4 = 0; k4 < 16; k4++) {
        float4 xv[4];
#pragma unroll
        for (int i = 0; i < 4; i++) xv[i] = xs4[(rl + 16 * i) * 17 + k4];
#pragma unroll
        for (int sub = 0; sub < 4; sub++) {
            int k = k4 * 4 + sub;
            const ulonglong2* wp = (const ulonglong2*)(Ws4 + k * 16 + cg * 2);
            ulonglong2 wA = wp[0], wB = wp[1];
#pragma unroll
            for (int i = 0; i < 4; i++) {
                float xk = (sub == 0) ? xv[i].x : (sub == 1) ? xv[i].y : (sub == 2) ? xv[i].z : xv[i].w;
                unsigned long long s = pack2(xk, xk);
                fma2(a[i][0], s, wA.x);
                fma2(a[i][1], s, wA.y);
                fma2(a[i][2], s, wB.x);
                fma2(a[i][3], s, wB.y);
            }
        }
    }

#pragma unroll
    for (int i = 0; i < 4; i++) {
        int row = rowbase + rl + 16 * i;
        if (row >= NN) continue;
        float2 p0 = unpack2(a[i][0]), p1 = unpack2(a[i][1]);
        float2 p2 = unpack2(a[i][2]), p3 = unpack2(a[i][3]);
        size_t o = (size_t)row * 16 + cg * 2;
        float4 x0 = g_x4[o], x1 = g_x4[o + 1];
        x0 = make_float4(sp(x0.x + p0.x), sp(x0.y + p0.y), sp(x0.z + p1.x), sp(x0.w + p1.y));
        x1 = make_float4(sp(x1.x + p2.x), sp(x1.y + p2.y), sp(x1.z + p3.x), sp(x1.w + p3.y));
        int bg = batch[row];
        red_add_v4((float*)(g_gsum4 + (size_t)bg * 16 + cg * 2), x0);
        red_add_v4((float*)(g_gsum4 + (size_t)bg * 16 + cg * 2 + 1), x1);
        if (cg == 0) red_add_f(&g_gcnt[bg], 1.0f);
    }
}

// ---------------- edge kernel: unsorted, 16 lanes/edge, packed-fma filter ----------------
__global__ void k_edge(const int* __restrict__ src, const int* __restrict__ dst,
                       const float* __restrict__ We, const float* __restrict__ be,
                       const float* __restrict__ ea) {
    __shared__ ulonglong2 Wp[NRBF * 16];   // We rows as f32x2 pairs
    __shared__ ulonglong2 bep[16];
    int t = threadIdx.x;
    if (t < NRBF * 16) Wp[t] = ((const ulonglong2*)We)[t];
    if (t >= NRBF * 16 && t < NRBF * 16 + 16) bep[t - NRBF * 16] = ((const ulonglong2*)be)[t - NRBF * 16];
    __syncthreads();

    int wid = t >> 5, lane = t & 31;
    int sub = lane >> 4;
    int sl  = lane & 15;
    int e = blockIdx.x * 16 + wid * 2 + sub;
    if (e >= NE) return;

    int s = src[e];
    int d = dst[e];
    float dist = ea[e];

    // issue the gather as early as possible
    float4 hv = __ldg(g_h4 + (size_t)s * 16 + sl);

    float ev = 0.0f;
    if (sl < NRBF) {
        float tt = dist - 0.66666667f * (float)sl;
        ev = __expf(-1.125f * tt * tt);
    }

    ulonglong2 bv = bep[sl];
    unsigned long long f0 = bv.x, f1 = bv.y;
#pragma unroll
    for (int r = 0; r < NRBF; r++) {
        float er = __shfl_sync(0xffffffffu, ev, (lane & 16) + r);
        unsigned long long sdup = pack2(er, er);
        ulonglong2 w = Wp[r * 16 + sl];
        fma2(f0, sdup, w.x);
        fma2(f1, sdup, w.y);
    }
    float2 fa = unpack2(f0), fb = unpack2(f1);
    float4 m = make_float4(hv.x * fa.x, hv.y * fa.y, hv.z * fb.x, hv.w * fb.y);
    red_add_v4((float*)(g_agg4 + (size_t)d * 16 + sl), m);
}

// ---------------- head: one block (128 threads) per graph ----------------
__global__ void k_head(const float* __restrict__ Wsm, const float* __restrict__ bsm,
                       const float* __restrict__ Wbg1, const float* __restrict__ bbg1,
                       const float* __restrict__ Wbg2, const float* __restrict__ bbg2,
                       const float* __restrict__ Weh1, const float* __restrict__ beh1,
                       const float* __restrict__ Weh2, const float* __restrict__ beh2,
                       float* __restrict__ out) {
    __shared__ float cs[NF];
    __shared__ float c2[2 * NH];
    __shared__ float red[128];

    int g = blockIdx.x, t = threadIdx.x;
    const float* gsum = (const float*)g_gsum4;

    if (t < NF) {
        float cnt = fmaxf(g_gcnt[g], 1.0f);
        cs[t] = gsum[(size_t)g * NF + t] / cnt;
    }
    __syncthreads();

    {
        float acc = bsm[t];
#pragma unroll 8
        for (int k = 0; k < NF; k++) acc += cs[k] * Wsm[k * 128 + t];
        c2[t] = fmaxf(acc, 0.0f);
    }
    __syncthreads();

    float partial;
    if (t < NH) {
        float acc = bbg1[t];
#pragma unroll 8
        for (int k = 0; k < 2 * NH; k++) acc += c2[k] * Wbg1[k * NH + t];
        partial = fmaxf(acc, 0.0f) * Wbg2[t];
    } else {
        int j = t - NH;
        float acc = beh1[j];
#pragma unroll 8
        for (int k = 0; k < 2 * NH; k++) acc += c2[k] * Weh1[k * NH + j];
        partial = fmaxf(acc, 0.0f) * Weh2[j];
    }
    red[t] = partial;
    __syncthreads();

    int base = t & 64;
    int l = t & 63;
#pragma unroll
    for (int s = 32; s > 0; s >>= 1) {
        if (l < s) red[base + l] += red[base + l + s];
        __syncthreads();
    }
    if (t == 0)  out[g]      = red[0]  + bbg2[0];
    if (t == 64) out[NG + g] = red[64] + beh2[0];
}

// ---------------- launch ----------------
extern "C" void kernel_launch(void* const* d_in, const int* in_sizes, int n_in,
                              void* d_out, int out_size) {
    const int*   x_ids = (const int*)d_in[0];
    const int*   eidx  = (const int*)d_in[1];
    const float* ea    = (const float*)d_in[2];
    const int*   batch = (const int*)d_in[3];
    const float* emb   = (const float*)d_in[4];
    const float* W1    = (const float*)d_in[5];
    const float* b1    = (const float*)d_in[6];
    const float* We    = (const float*)d_in[7];
    const float* be    = (const float*)d_in[8];
    const float* W2    = (const float*)d_in[9];
    const float* b2    = (const float*)d_in[10];
    const float* Wsm   = (const float*)d_in[11];
    const float* bsm   = (const float*)d_in[12];
    const float* Wbg1  = (const float*)d_in[13];
    const float* bbg1  = (const float*)d_in[14];
    const float* Wbg2  = (const float*)d_in[15];
    const float* bbg2  = (const float*)d_in[16];
    const float* Weh1  = (const float*)d_in[17];
    const float* beh1  = (const float*)d_in[18];
    const float* Weh2  = (const float*)d_in[19];
    const float* beh2  = (const float*)d_in[20];

    const int* src = eidx;
    const int* dst = eidx + NE;
    float* out = (float*)d_out;

    const int GB = (NN + 63) / 64;

    k_emb_w1<<<NTYPE, 64>>>(emb, W1, b1);
    k_embed0<<<(NN * 16 + 255) / 256, 256>>>(x_ids, (const float4*)emb);

    // conv0
    k_edge<<<NE / 16, 256>>>(src, dst, We, be, ea);
    k_gemm_fused<<<GB, 256>>>(W2, b2, W1 + 1 * NF * NF, b1 + 1 * NF);
    // conv1
    k_edge<<<NE / 16, 256>>>(src, dst, We + 1 * NRBF * NF, be + 1 * NF, ea);
    k_gemm_fused<<<GB, 256>>>(W2 + 1 * NF * NF, b2 + 1 * NF, W1 + 2 * NF * NF, b1 + 2 * NF);
    // conv2
    k_edge<<<NE / 16, 256>>>(src, dst, We + 2 * NRBF * NF, be + 2 * NF, ea);
    k_gemm_final<<<GB, 128>>>(W2 + 2 * NF * NF, b2 + 2 * NF, batch);

    k_head<<<NG, 128>>>(Wsm, bsm, Wbg1, bbg1, Wbg2, bbg2, Weh1, beh1, Weh2, beh2, out);
}

// round 8
// speedup vs baseline: 1.8103x; 1.8103x over previous
#include <cuda_runtime.h>
#include <math.h>

#define NN   50000
#define NE   800000
#define NF   64
#define NRBF 10
#define NG   512
#define NH   64
#define NTYPE 95
#define NBIN 1024
#define NROW (NBIN + 2)

// ---------------- scratch (device globals) ----------------
__device__ float4 g_x4[NN * 16];       // node features
__device__ float4 g_h4[NN * 16];       // pre-message transform
__device__ float4 g_agg4[NN * 16];     // scatter accumulator
__device__ float4 g_gsum4[NG * 16];    // per-graph sums
__device__ float  g_gcnt[NG];          // per-graph counts
__device__ float  g_hemb[NTYPE * NF];  // emb @ W1[0] + b1[0]
__device__ float4 g_ftab[3 * NROW * 16];  // per-conv filter tables f(dist)

// ---------------- helpers ----------------
__device__ __forceinline__ void red_add_v4(float* p, float4 v) {
    asm volatile("red.global.add.v4.f32 [%0], {%1,%2,%3,%4};"
                 :: "l"(p), "f"(v.x), "f"(v.y), "f"(v.z), "f"(v.w) : "memory");
}
__device__ __forceinline__ void red_add_f(float* p, float v) {
    asm volatile("red.global.add.f32 [%0], %1;" :: "l"(p), "f"(v) : "memory");
}
__device__ __forceinline__ unsigned long long pack2(float x, float y) {
    unsigned long long r;
    asm("mov.b64 %0, {%1,%2};" : "=l"(r) : "f"(x), "f"(y));
    return r;
}
__device__ __forceinline__ void fma2(unsigned long long& d, unsigned long long a, unsigned long long b) {
    asm("fma.rn.f32x2 %0, %1, %2, %3;" : "=l"(d) : "l"(a), "l"(b), "l"(d));
}
__device__ __forceinline__ float2 unpack2(unsigned long long v) {
    float2 f;
    asm("mov.b64 {%0,%1}, %2;" : "=f"(f.x), "=f"(f.y) : "l"(v));
    return f;
}
__device__ __forceinline__ float sp(float x) {   // stable softplus
    return fmaxf(x, 0.0f) + log1pf(expf(-fabsf(x)));
}

// ---------------- tiny GEMM: g_hemb = emb @ W1[0] + b1[0]  (95 x 64) ----------------
__global__ void k_emb_w1(const float* __restrict__ emb, const float* __restrict__ W,
                         const float* __restrict__ b) {
    __shared__ float Ws[NF * NF];
    int t = threadIdx.x;
    for (int i = t; i < NF * NF; i += 64) Ws[i] = W[i];
    __syncthreads();
    int row = blockIdx.x;
    float acc = b[t];
    const float* er = emb + row * NF;
#pragma unroll 8
    for (int k = 0; k < NF; k++) acc += er[k] * Ws[k * NF + t];
    g_hemb[row * NF + t] = acc;
}

// ---------------- filter tables: ftab[conv][bin][c] = rbf(d_bin) @ We + be ----------------
__global__ void k_ftable(const float* __restrict__ We, const float* __restrict__ be) {
    int bin  = blockIdx.x;        // 0..NROW-1
    int conv = blockIdx.y;        // 0..2
    int c    = threadIdx.x;       // 0..63
    float d = (float)bin * (6.0f / (float)NBIN);
    const float* Wc = We + conv * NRBF * NF;
    float acc = be[conv * NF + c];
#pragma unroll
    for (int r = 0; r < NRBF; r++) {
        float tt = d - 0.66666667f * (float)r;
        acc += expf(-1.125f * tt * tt) * Wc[r * NF + c];
    }
    ((float*)g_ftab)[(conv * NROW + bin) * NF + c] = acc;
}

// ---------------- conv0 front: x = emb[ids], h = hemb[ids], agg = 0, pool zero ----------------
__global__ void k_embed0(const int* __restrict__ ids, const float4* __restrict__ emb4) {
    int t = blockIdx.x * blockDim.x + threadIdx.x;
    if (t < NG * 16) g_gsum4[t] = make_float4(0.f, 0.f, 0.f, 0.f);
    if (t < NG) g_gcnt[t] = 0.0f;
    if (t >= NN * 16) return;
    int n = t >> 4, c = t & 15;
    int id = ids[n];
    g_x4[t] = emb4[(size_t)id * 16 + c];
    g_h4[t] = ((const float4*)g_hemb)[(size_t)id * 16 + c];
    g_agg4[t] = make_float4(0.f, 0.f, 0.f, 0.f);
}

// ---------------- node GEMM: 64 rows/block, 128 thr, 4 rows x 8 cols/thread ----------------
// mode 0: g_h = g_x @ W + b ; zero g_agg
// mode 1: g_x = softplus(g_x + g_agg @ W + b)
// mode 2: like 1, result goes straight to graph pool
__global__ __launch_bounds__(128) void k_node_gemm(
        const float* __restrict__ W, const float* __restrict__ b, int mode,
        const int* __restrict__ batch) {
    __shared__ float4 Ws4[NF * 16];
    __shared__ float4 xs4[64 * 17];
    __shared__ float  bs[NF];

    int t = threadIdx.x;
    const float4* W4 = (const float4*)W;
#pragma unroll
    for (int i = 0; i < 8; i++) Ws4[t + 128 * i] = W4[t + 128 * i];
    if (t < NF) bs[t] = b[t];

    int rowbase = blockIdx.x * 64;
    const float4* in4 = (mode == 0) ? g_x4 : g_agg4;

#pragma unroll
    for (int i = 0; i < 8; i++) {
        int idx = t + 128 * i;
        int lr = idx >> 4, c = idx & 15;
        int row = rowbase + lr;
        if (row < NN) xs4[lr * 17 + c] = in4[(size_t)row * 16 + c];
    }
    __syncthreads();

    int cg = t & 7;
    int rl = t >> 3;

    unsigned long long a[4][4];
    {
        int cb = cg * 8;
        unsigned long long b0 = pack2(bs[cb + 0], bs[cb + 1]);
        unsigned long long b1 = pack2(bs[cb + 2], bs[cb + 3]);
        unsigned long long b2 = pack2(bs[cb + 4], bs[cb + 5]);
        unsigned long long b3 = pack2(bs[cb + 6], bs[cb + 7]);
#pragma unroll
        for (int i = 0; i < 4; i++) { a[i][0] = b0; a[i][1] = b1; a[i][2] = b2; a[i][3] = b3; }
    }

#pragma unroll 4
    for (int k4 = 0; k4 < 16; k4++) {
        float4 xv[4];
#pragma unroll
        for (int i = 0; i < 4; i++) xv[i] = xs4[(rl + 16 * i) * 17 + k4];
#pragma unroll
        for (int sub = 0; sub < 4; sub++) {
            int k = k4 * 4 + sub;
            const ulonglong2* wp = (const ulonglong2*)(Ws4 + k * 16 + cg * 2);
            ulonglong2 wA = wp[0];
            ulonglong2 wB = wp[1];
#pragma unroll
            for (int i = 0; i < 4; i++) {
                float xk = (sub == 0) ? xv[i].x : (sub == 1) ? xv[i].y : (sub == 2) ? xv[i].z : xv[i].w;
                unsigned long long s = pack2(xk, xk);
                fma2(a[i][0], s, wA.x);
                fma2(a[i][1], s, wA.y);
                fma2(a[i][2], s, wB.x);
                fma2(a[i][3], s, wB.y);
            }
        }
    }

#pragma unroll
    for (int i = 0; i < 4; i++) {
        int row = rowbase + rl + 16 * i;
        if (row >= NN) continue;
        float2 p0 = unpack2(a[i][0]), p1 = unpack2(a[i][1]);
        float2 p2 = unpack2(a[i][2]), p3 = unpack2(a[i][3]);
        float4 r0 = make_float4(p0.x, p0.y, p1.x, p1.y);
        float4 r1 = make_float4(p2.x, p2.y, p3.x, p3.y);
        size_t o = (size_t)row * 16 + cg * 2;
        if (mode == 0) {
            g_h4[o]     = r0;
            g_h4[o + 1] = r1;
            g_agg4[o]     = make_float4(0.f, 0.f, 0.f, 0.f);
            g_agg4[o + 1] = make_float4(0.f, 0.f, 0.f, 0.f);
        } else {
            float4 x0 = g_x4[o], x1 = g_x4[o + 1];
            x0 = make_float4(sp(x0.x + r0.x), sp(x0.y + r0.y), sp(x0.z + r0.z), sp(x0.w + r0.w));
            x1 = make_float4(sp(x1.x + r1.x), sp(x1.y + r1.y), sp(x1.z + r1.z), sp(x1.w + r1.w));
            if (mode == 1) {
                g_x4[o]     = x0;
                g_x4[o + 1] = x1;
            } else {
                int bg = batch[row];
                red_add_v4((float*)(g_gsum4 + (size_t)bg * 16 + cg * 2), x0);
                red_add_v4((float*)(g_gsum4 + (size_t)bg * 16 + cg * 2 + 1), x1);
                if (cg == 0) red_add_f(&g_gcnt[bg], 1.0f);
            }
        }
    }
}

// ---------------- edge kernel: table-lerp filter, 16 lanes/edge ----------------
__global__ void k_edge(const int* __restrict__ src, const int* __restrict__ dst,
                       const float* __restrict__ ea, int conv) {
    int t = threadIdx.x;
    int wid = t >> 5, lane = t & 31;
    int sub = lane >> 4;          // edge within warp
    int sl  = lane & 15;          // float4 slot
    int e = blockIdx.x * 16 + wid * 2 + sub;
    if (e >= NE) return;

    int s = src[e];
    int d = dst[e];
    float dist = ea[e];

    // issue the gather as early as possible
    float4 hv = __ldg(g_h4 + (size_t)s * 16 + sl);

    // filter via table lerp
    float bf = dist * ((float)NBIN / 6.0f);
    int bin = (int)bf;
    float fr = bf - (float)bin;
    const float4* row = g_ftab + ((size_t)conv * NROW + bin) * 16 + sl;
    float4 f0 = __ldg(row);
    float4 f1 = __ldg(row + 16);
    float4 f;
    f.x = fmaf(fr, f1.x - f0.x, f0.x);
    f.y = fmaf(fr, f1.y - f0.y, f0.y);
    f.z = fmaf(fr, f1.z - f0.z, f0.z);
    f.w = fmaf(fr, f1.w - f0.w, f0.w);

    float4 m = make_float4(hv.x * f.x, hv.y * f.y, hv.z * f.z, hv.w * f.w);
    red_add_v4((float*)(g_agg4 + (size_t)d * 16 + sl), m);
}

// ---------------- head: one block (128 threads) per graph ----------------
__global__ void k_head(const float* __restrict__ Wsm, const float* __restrict__ bsm,
                       const float* __restrict__ Wbg1, const float* __restrict__ bbg1,
                       const float* __restrict__ Wbg2, const float* __restrict__ bbg2,
                       const float* __restrict__ Weh1, const float* __restrict__ beh1,
                       const float* __restrict__ Weh2, const float* __restrict__ beh2,
                       float* __restrict__ out) {
    __shared__ float cs[NF];
    __shared__ float c2[2 * NH];
    __shared__ float red[128];

    int g = blockIdx.x, t = threadIdx.x;
    const float* gsum = (const float*)g_gsum4;

    if (t < NF) {
        float cnt = fmaxf(g_gcnt[g], 1.0f);
        cs[t] = gsum[(size_t)g * NF + t] / cnt;
    }
    __syncthreads();

    {
        float acc = bsm[t];
#pragma unroll 8
        for (int k = 0; k < NF; k++) acc += cs[k] * Wsm[k * 128 + t];
        c2[t] = fmaxf(acc, 0.0f);
    }
    __syncthreads();

    float partial;
    if (t < NH) {
        float acc = bbg1[t];
#pragma unroll 8
        for (int k = 0; k < 2 * NH; k++) acc += c2[k] * Wbg1[k * NH + t];
        partial = fmaxf(acc, 0.0f) * Wbg2[t];
    } else {
        int j = t - NH;
        float acc = beh1[j];
#pragma unroll 8
        for (int k = 0; k < 2 * NH; k++) acc += c2[k] * Weh1[k * NH + j];
        partial = fmaxf(acc, 0.0f) * Weh2[j];
    }
    red[t] = partial;
    __syncthreads();

    int base = t & 64;
    int l = t & 63;
#pragma unroll
    for (int s = 32; s > 0; s >>= 1) {
        if (l < s) red[base + l] += red[base + l + s];
        __syncthreads();
    }
    if (t == 0)  out[g]      = red[0]  + bbg2[0];
    if (t == 64) out[NG + g] = red[64] + beh2[0];
}

// ---------------- launch ----------------
extern "C" void kernel_launch(void* const* d_in, const int* in_sizes, int n_in,
                              void* d_out, int out_size) {
    const int*   x_ids = (const int*)d_in[0];
    const int*   eidx  = (const int*)d_in[1];
    const float* ea    = (const float*)d_in[2];
    const int*   batch = (const int*)d_in[3];
    const float* emb   = (const float*)d_in[4];
    const float* W1    = (const float*)d_in[5];
    const float* b1    = (const float*)d_in[6];
    const float* We    = (const float*)d_in[7];
    const float* be    = (const float*)d_in[8];
    const float* W2    = (const float*)d_in[9];
    const float* b2    = (const float*)d_in[10];
    const float* Wsm   = (const float*)d_in[11];
    const float* bsm   = (const float*)d_in[12];
    const float* Wbg1  = (const float*)d_in[13];
    const float* bbg1  = (const float*)d_in[14];
    const float* Wbg2  = (const float*)d_in[15];
    const float* bbg2  = (const float*)d_in[16];
    const float* Weh1  = (const float*)d_in[17];
    const float* beh1  = (const float*)d_in[18];
    const float* Weh2  = (const float*)d_in[19];
    const float* beh2  = (const float*)d_in[20];

    const int* src = eidx;
    const int* dst = eidx + NE;
    float* out = (float*)d_out;

    const int GB = (NN + 63) / 64;

    k_emb_w1<<<NTYPE, 64>>>(emb, W1, b1);
    dim3 tg(NROW, 3);
    k_ftable<<<tg, 64>>>(We, be);
    k_embed0<<<(NN * 16 + 255) / 256, 256>>>(x_ids, (const float4*)emb);

    for (int i = 0; i < 3; i++) {
        if (i > 0)
            k_node_gemm<<<GB, 128>>>(W1 + i * NF * NF, b1 + i * NF, 0, nullptr);
        k_edge<<<NE / 16, 256>>>(src, dst, ea, i);
        k_node_gemm<<<GB, 128>>>(W2 + i * NF * NF, b2 + i * NF, (i == 2) ? 2 : 1, batch);
    }

    k_head<<<NG, 128>>>(Wsm, bsm, Wbg1, bbg1, Wbg2, bbg2, Weh1, beh1, Weh2, beh2, out);
}

// round 9
// speedup vs baseline: 1.8421x; 1.0176x over previous
#include <cuda_runtime.h>
#include <cuda_bf16.h>
#include <math.h>

#define NN   50000
#define NE   800000
#define NF   64
#define NRBF 10
#define NG   512
#define NH   64
#define NTYPE 95
#define NBIN 1024
#define NROW (NBIN + 2)

// ---------------- scratch (device globals) ----------------
__device__ float4 g_x4[NN * 16];         // node features (fp32)
__device__ uint2  g_hb[NN * 16];         // pre-message transform, bf16x2 pairs (64 bf16/node)
__device__ float4 g_agg4[NN * 16];       // scatter accumulator (fp32)
__device__ float4 g_gsum4[NG * 16];      // per-graph sums
__device__ float  g_gcnt[NG];            // per-graph counts
__device__ float  g_hemb[NTYPE * NF];    // emb @ W1[0] + b1[0] (fp32)
__device__ uint2  g_ftabh[3 * NROW * 16]; // per-conv filter tables, bf16

// ---------------- helpers ----------------
__device__ __forceinline__ void red_add_v4(float* p, float4 v) {
    asm volatile("red.global.add.v4.f32 [%0], {%1,%2,%3,%4};"
                 :: "l"(p), "f"(v.x), "f"(v.y), "f"(v.z), "f"(v.w) : "memory");
}
__device__ __forceinline__ void red_add_f(float* p, float v) {
    asm volatile("red.global.add.f32 [%0], %1;" :: "l"(p), "f"(v) : "memory");
}
__device__ __forceinline__ unsigned long long pack2(float x, float y) {
    unsigned long long r;
    asm("mov.b64 %0, {%1,%2};" : "=l"(r) : "f"(x), "f"(y));
    return r;
}
__device__ __forceinline__ void fma2(unsigned long long& d, unsigned long long a, unsigned long long b) {
    asm("fma.rn.f32x2 %0, %1, %2, %3;" : "=l"(d) : "l"(a), "l"(b), "l"(d));
}
__device__ __forceinline__ float2 unpack2(unsigned long long v) {
    float2 f;
    asm("mov.b64 {%0,%1}, %2;" : "=f"(f.x), "=f"(f.y) : "l"(v));
    return f;
}
__device__ __forceinline__ float2 bf2f(unsigned u) {
    __nv_bfloat162 h = *reinterpret_cast<__nv_bfloat162*>(&u);
    return __bfloat1622float2(h);
}
__device__ __forceinline__ unsigned f2bf(float x, float y) {
    __nv_bfloat162 h = __floats2bfloat162_rn(x, y);
    return *reinterpret_cast<unsigned*>(&h);
}
__device__ __forceinline__ float sp(float x) {   // stable softplus
    return fmaxf(x, 0.0f) + log1pf(expf(-fabsf(x)));
}

// ---------------- tiny GEMM: g_hemb = emb @ W1[0] + b1[0]  (95 x 64) ----------------
__global__ void k_emb_w1(const float* __restrict__ emb, const float* __restrict__ W,
                         const float* __restrict__ b) {
    __shared__ float Ws[NF * NF];
    int t = threadIdx.x;
    for (int i = t; i < NF * NF; i += 64) Ws[i] = W[i];
    __syncthreads();
    int row = blockIdx.x;
    float acc = b[t];
    const float* er = emb + row * NF;
#pragma unroll 8
    for (int k = 0; k < NF; k++) acc += er[k] * Ws[k * NF + t];
    g_hemb[row * NF + t] = acc;
}

// ---------------- filter tables (bf16): 32 thr, 2 features/thread ----------------
__global__ void k_ftable(const float* __restrict__ We, const float* __restrict__ be) {
    int bin  = blockIdx.x;        // 0..NROW-1
    int conv = blockIdx.y;        // 0..2
    int t    = threadIdx.x;       // 0..31 -> features 2t, 2t+1
    float d = (float)bin * (6.0f / (float)NBIN);
    const float* Wc = We + conv * NRBF * NF;
    float a0 = be[conv * NF + 2 * t];
    float a1 = be[conv * NF + 2 * t + 1];
#pragma unroll
    for (int r = 0; r < NRBF; r++) {
        float tt = d - 0.66666667f * (float)r;
        float e = expf(-1.125f * tt * tt);
        a0 += e * Wc[r * NF + 2 * t];
        a1 += e * Wc[r * NF + 2 * t + 1];
    }
    ((unsigned*)g_ftabh)[((size_t)conv * NROW + bin) * 32 + t] = f2bf(a0, a1);
}

// ---------------- conv0 front: x = emb[ids], h = bf16(hemb[ids]), agg = 0, pool zero ----
__global__ void k_embed0(const int* __restrict__ ids, const float4* __restrict__ emb4) {
    int t = blockIdx.x * blockDim.x + threadIdx.x;
    if (t < NG * 16) g_gsum4[t] = make_float4(0.f, 0.f, 0.f, 0.f);
    if (t < NG) g_gcnt[t] = 0.0f;
    if (t >= NN * 16) return;
    int n = t >> 4, c = t & 15;
    int id = ids[n];
    g_x4[t] = emb4[(size_t)id * 16 + c];
    float4 hv = ((const float4*)g_hemb)[(size_t)id * 16 + c];
    g_hb[t] = make_uint2(f2bf(hv.x, hv.y), f2bf(hv.z, hv.w));
    g_agg4[t] = make_float4(0.f, 0.f, 0.f, 0.f);
}

// ---------------- node GEMM: 64 rows/block, 128 thr, 4 rows x 8 cols/thread ----------------
// mode 0: g_hb = bf16(g_x @ W + b) ; zero g_agg
// mode 1: g_x = softplus(g_x + g_agg @ W + b)
// mode 2: like 1, result goes straight to graph pool
__global__ __launch_bounds__(128) void k_node_gemm(
        const float* __restrict__ W, const float* __restrict__ b, int mode,
        const int* __restrict__ batch) {
    __shared__ float4 Ws4[NF * 16];
    __shared__ float4 xs4[64 * 17];
    __shared__ float  bs[NF];

    int t = threadIdx.x;
    const float4* W4 = (const float4*)W;
#pragma unroll
    for (int i = 0; i < 8; i++) Ws4[t + 128 * i] = W4[t + 128 * i];
    if (t < NF) bs[t] = b[t];

    int rowbase = blockIdx.x * 64;
    const float4* in4 = (mode == 0) ? g_x4 : g_agg4;

#pragma unroll
    for (int i = 0; i < 8; i++) {
        int idx = t + 128 * i;
        int lr = idx >> 4, c = idx & 15;
        int row = rowbase + lr;
        if (row < NN) xs4[lr * 17 + c] = in4[(size_t)row * 16 + c];
    }
    __syncthreads();

    int cg = t & 7;
    int rl = t >> 3;

    unsigned long long a[4][4];
    {
        int cb = cg * 8;
        unsigned long long b0 = pack2(bs[cb + 0], bs[cb + 1]);
        unsigned long long b1 = pack2(bs[cb + 2], bs[cb + 3]);
        unsigned long long b2 = pack2(bs[cb + 4], bs[cb + 5]);
        unsigned long long b3 = pack2(bs[cb + 6], bs[cb + 7]);
#pragma unroll
        for (int i = 0; i < 4; i++) { a[i][0] = b0; a[i][1] = b1; a[i][2] = b2; a[i][3] = b3; }
    }

#pragma unroll 4
    for (int k4 = 0; k4 < 16; k4++) {
        float4 xv[4];
#pragma unroll
        for (int i = 0; i < 4; i++) xv[i] = xs4[(rl + 16 * i) * 17 + k4];
#pragma unroll
        for (int sub = 0; sub < 4; sub++) {
            int k = k4 * 4 + sub;
            const ulonglong2* wp = (const ulonglong2*)(Ws4 + k * 16 + cg * 2);
            ulonglong2 wA = wp[0];
            ulonglong2 wB = wp[1];
#pragma unroll
            for (int i = 0; i < 4; i++) {
                float xk = (sub == 0) ? xv[i].x : (sub == 1) ? xv[i].y : (sub == 2) ? xv[i].z : xv[i].w;
                unsigned long long s = pack2(xk, xk);
                fma2(a[i][0], s, wA.x);
                fma2(a[i][1], s, wA.y);
                fma2(a[i][2], s, wB.x);
                fma2(a[i][3], s, wB.y);
            }
        }
    }

#pragma unroll
    for (int i = 0; i < 4; i++) {
        int row = rowbase + rl + 16 * i;
        if (row >= NN) continue;
        float2 p0 = unpack2(a[i][0]), p1 = unpack2(a[i][1]);
        float2 p2 = unpack2(a[i][2]), p3 = unpack2(a[i][3]);
        float4 r0 = make_float4(p0.x, p0.y, p1.x, p1.y);
        float4 r1 = make_float4(p2.x, p2.y, p3.x, p3.y);
        size_t o = (size_t)row * 16 + cg * 2;
        if (mode == 0) {
            g_hb[o]     = make_uint2(f2bf(r0.x, r0.y), f2bf(r0.z, r0.w));
            g_hb[o + 1] = make_uint2(f2bf(r1.x, r1.y), f2bf(r1.z, r1.w));
            g_agg4[o]     = make_float4(0.f, 0.f, 0.f, 0.f);
            g_agg4[o + 1] = make_float4(0.f, 0.f, 0.f, 0.f);
        } else {
            float4 x0 = g_x4[o], x1 = g_x4[o + 1];
            x0 = make_float4(sp(x0.x + r0.x), sp(x0.y + r0.y), sp(x0.z + r0.z), sp(x0.w + r0.w));
            x1 = make_float4(sp(x1.x + r1.x), sp(x1.y + r1.y), sp(x1.z + r1.z), sp(x1.w + r1.w));
            if (mode == 1) {
                g_x4[o]     = x0;
                g_x4[o + 1] = x1;
            } else {
                int bg = batch[row];
                red_add_v4((float*)(g_gsum4 + (size_t)bg * 16 + cg * 2), x0);
                red_add_v4((float*)(g_gsum4 + (size_t)bg * 16 + cg * 2 + 1), x1);
                if (cg == 0) red_add_f(&g_gcnt[bg], 1.0f);
            }
        }
    }
}

// ---------------- edge kernel: bf16 gather + bf16 table lerp, fp32 RED ----------------
__global__ void k_edge(const int* __restrict__ src, const int* __restrict__ dst,
                       const float* __restrict__ ea, int conv) {
    int t = threadIdx.x;
    int wid = t >> 5, lane = t & 31;
    int sub = lane >> 4;          // edge within warp
    int sl  = lane & 15;          // feature slot (4 feats)
    int e = blockIdx.x * 16 + wid * 2 + sub;
    if (e >= NE) return;

    int s = src[e];
    int d = dst[e];
    float dist = ea[e];

    // gather h (bf16x2 pairs, 8B/lane)
    uint2 hv2 = __ldg(g_hb + (size_t)s * 16 + sl);

    // filter via bf16 table lerp
    float bf = dist * ((float)NBIN / 6.0f);
    int bin = (int)bf;
    float fr = bf - (float)bin;
    const uint2* row = g_ftabh + ((size_t)conv * NROW + bin) * 16 + sl;
    uint2 f0b = __ldg(row);
    uint2 f1b = __ldg(row + 16);

    float2 h01 = bf2f(hv2.x), h23 = bf2f(hv2.y);
    float2 f0a = bf2f(f0b.x), f0c = bf2f(f0b.y);
    float2 f1a = bf2f(f1b.x), f1c = bf2f(f1b.y);

    float4 m;
    m.x = h01.x * fmaf(fr, f1a.x - f0a.x, f0a.x);
    m.y = h01.y * fmaf(fr, f1a.y - f0a.y, f0a.y);
    m.z = h23.x * fmaf(fr, f1c.x - f0c.x, f0c.x);
    m.w = h23.y * fmaf(fr, f1c.y - f0c.y, f0c.y);

    red_add_v4((float*)(g_agg4 + (size_t)d * 16 + sl), m);
}

// ---------------- head: one block (128 threads) per graph ----------------
__global__ void k_head(const float* __restrict__ Wsm, const float* __restrict__ bsm,
                       const float* __restrict__ Wbg1, const float* __restrict__ bbg1,
                       const float* __restrict__ Wbg2, const float* __restrict__ bbg2,
                       const float* __restrict__ Weh1, const float* __restrict__ beh1,
                       const float* __restrict__ Weh2, const float* __restrict__ beh2,
                       float* __restrict__ out) {
    __shared__ float cs[NF];
    __shared__ float c2[2 * NH];
    __shared__ float red[128];

    int g = blockIdx.x, t = threadIdx.x;
    const float* gsum = (const float*)g_gsum4;

    if (t < NF) {
        float cnt = fmaxf(g_gcnt[g], 1.0f);
        cs[t] = gsum[(size_t)g * NF + t] / cnt;
    }
    __syncthreads();

    {
        float acc = bsm[t];
#pragma unroll 8
        for (int k = 0; k < NF; k++) acc += cs[k] * Wsm[k * 128 + t];
        c2[t] = fmaxf(acc, 0.0f);
    }
    __syncthreads();

    float partial;
    if (t < NH) {
        float acc = bbg1[t];
#pragma unroll 8
        for (int k = 0; k < 2 * NH; k++) acc += c2[k] * Wbg1[k * NH + t];
        partial = fmaxf(acc, 0.0f) * Wbg2[t];
    } else {
        int j = t - NH;
        float acc = beh1[j];
#pragma unroll 8
        for (int k = 0; k < 2 * NH; k++) acc += c2[k] * Weh1[k * NH + j];
        partial = fmaxf(acc, 0.0f) * Weh2[j];
    }
    red[t] = partial;
    __syncthreads();

    int base = t & 64;
    int l = t & 63;
#pragma unroll
    for (int s = 32; s > 0; s >>= 1) {
        if (l < s) red[base + l] += red[base + l + s];
        __syncthreads();
    }
    if (t == 0)  out[g]      = red[0]  + bbg2[0];
    if (t == 64) out[NG + g] = red[64] + beh2[0];
}

// ---------------- launch ----------------
extern "C" void kernel_launch(void* const* d_in, const int* in_sizes, int n_in,
                              void* d_out, int out_size) {
    const int*   x_ids = (const int*)d_in[0];
    const int*   eidx  = (const int*)d_in[1];
    const float* ea    = (const float*)d_in[2];
    const int*   batch = (const int*)d_in[3];
    const float* emb   = (const float*)d_in[4];
    const float* W1    = (const float*)d_in[5];
    const float* b1    = (const float*)d_in[6];
    const float* We    = (const float*)d_in[7];
    const float* be    = (const float*)d_in[8];
    const float* W2    = (const float*)d_in[9];
    const float* b2    = (const float*)d_in[10];
    const float* Wsm   = (const float*)d_in[11];
    const float* bsm   = (const float*)d_in[12];
    const float* Wbg1  = (const float*)d_in[13];
    const float* bbg1  = (const float*)d_in[14];
    const float* Wbg2  = (const float*)d_in[15];
    const float* bbg2  = (const float*)d_in[16];
    const float* Weh1  = (const float*)d_in[17];
    const float* beh1  = (const float*)d_in[18];
    const float* Weh2  = (const float*)d_in[19];
    const float* beh2  = (const float*)d_in[20];

    const int* src = eidx;
    const int* dst = eidx + NE;
    float* out = (float*)d_out;

    const int GB = (NN + 63) / 64;

    k_emb_w1<<<NTYPE, 64>>>(emb, W1, b1);
    dim3 tg(NROW, 3);
    k_ftable<<<tg, 32>>>(We, be);
    k_embed0<<<(NN * 16 + 255) / 256, 256>>>(x_ids, (const float4*)emb);

    for (int i = 0; i < 3; i++) {
        if (i > 0)
            k_node_gemm<<<GB, 128>>>(W1 + i * NF * NF, b1 + i * NF, 0, nullptr);
        k_edge<<<NE / 16, 256>>>(src, dst, ea, i);
        k_node_gemm<<<GB, 128>>>(W2 + i * NF * NF, b2 + i * NF, (i == 2) ? 2 : 1, batch);
    }

    k_head<<<NG, 128>>>(Wsm, bsm, Wbg1, bbg1, Wbg2, bbg2, Weh1, beh1, Weh2, beh2, out);
}

// round 10
// speedup vs baseline: 1.8636x; 1.0117x over previous
#include <cuda_runtime.h>
#include <math.h>

#define NN   50000
#define NE   800000
#define NF   64
#define NRBF 10
#define NG   512
#define NH   64
#define NTYPE 95
#define NBIN 1024
#define NROW (NBIN + 2)

// ---------------- scratch (device globals) ----------------
__device__ float4 g_x4[NN * 16];       // node features
__device__ float4 g_h4[NN * 16];       // pre-message transform
__device__ float4 g_agg4[NN * 16];     // scatter accumulator
__device__ float4 g_gsum4[NG * 16];    // per-graph sums
__device__ float  g_gcnt[NG];          // per-graph counts
__device__ float  g_hemb[NTYPE * NF];  // emb @ W1[0] + b1[0]
__device__ float4 g_ftab[3 * NROW * 16];  // per-conv filter tables f(dist)

// ---------------- helpers ----------------
__device__ __forceinline__ void red_add_v4(float* p, float4 v) {
    asm volatile("red.global.add.v4.f32 [%0], {%1,%2,%3,%4};"
                 :: "l"(p), "f"(v.x), "f"(v.y), "f"(v.z), "f"(v.w) : "memory");
}
__device__ __forceinline__ void red_add_f(float* p, float v) {
    asm volatile("red.global.add.f32 [%0], %1;" :: "l"(p), "f"(v) : "memory");
}
__device__ __forceinline__ unsigned long long pack2(float x, float y) {
    unsigned long long r;
    asm("mov.b64 %0, {%1,%2};" : "=l"(r) : "f"(x), "f"(y));
    return r;
}
__device__ __forceinline__ void fma2(unsigned long long& d, unsigned long long a, unsigned long long b) {
    asm("fma.rn.f32x2 %0, %1, %2, %3;" : "=l"(d) : "l"(a), "l"(b), "l"(d));
}
__device__ __forceinline__ float2 unpack2(unsigned long long v) {
    float2 f;
    asm("mov.b64 {%0,%1}, %2;" : "=f"(f.x), "=f"(f.y) : "l"(v));
    return f;
}
__device__ __forceinline__ float sp(float x) {   // stable softplus
    return fmaxf(x, 0.0f) + log1pf(expf(-fabsf(x)));
}

// ---------------- tiny GEMM: g_hemb = emb @ W1[0] + b1[0]  (95 x 64) ----------------
__global__ void k_emb_w1(const float* __restrict__ emb, const float* __restrict__ W,
                         const float* __restrict__ b) {
    __shared__ float Ws[NF * NF];
    int t = threadIdx.x;
    for (int i = t; i < NF * NF; i += 64) Ws[i] = W[i];
    __syncthreads();
    int row = blockIdx.x;
    float acc = b[t];
    const float* er = emb + row * NF;
#pragma unroll 8
    for (int k = 0; k < NF; k++) acc += er[k] * Ws[k * NF + t];
    g_hemb[row * NF + t] = acc;
}

// ---------------- filter tables: ftab[conv][bin][c] = rbf(d_bin) @ We + be ----------------
__global__ void k_ftable(const float* __restrict__ We, const float* __restrict__ be) {
    int bin  = blockIdx.x;        // 0..NROW-1
    int conv = blockIdx.y;        // 0..2
    int c    = threadIdx.x;       // 0..63
    float d = (float)bin * (6.0f / (float)NBIN);
    const float* Wc = We + conv * NRBF * NF;
    float acc = be[conv * NF + c];
#pragma unroll
    for (int r = 0; r < NRBF; r++) {
        float tt = d - 0.66666667f * (float)r;
        acc += expf(-1.125f * tt * tt) * Wc[r * NF + c];
    }
    ((float*)g_ftab)[(conv * NROW + bin) * NF + c] = acc;
}

// ---------------- conv0 front: x = emb[ids], h = hemb[ids], agg = 0, pool zero ----------------
__global__ void k_embed0(const int* __restrict__ ids, const float4* __restrict__ emb4) {
    int t = blockIdx.x * blockDim.x + threadIdx.x;
    if (t < NG * 16) g_gsum4[t] = make_float4(0.f, 0.f, 0.f, 0.f);
    if (t < NG) g_gcnt[t] = 0.0f;
    if (t >= NN * 16) return;
    int n = t >> 4, c = t & 15;
    int id = ids[n];
    g_x4[t] = emb4[(size_t)id * 16 + c];
    g_h4[t] = ((const float4*)g_hemb)[(size_t)id * 16 + c];
    g_agg4[t] = make_float4(0.f, 0.f, 0.f, 0.f);
}

// ---------------- node GEMM: 64 rows/block, 128 thr, 4 rows x 8 cols/thread ----------------
// mode 0: g_h = g_x @ W + b ; zero g_agg
// mode 1: g_x = softplus(g_x + g_agg @ W + b)
// mode 2: like 1, result goes straight to graph pool
__global__ __launch_bounds__(128) void k_node_gemm(
        const float* __restrict__ W, const float* __restrict__ b, int mode,
        const int* __restrict__ batch) {
    __shared__ float4 Ws4[NF * 16];
    __shared__ float4 xs4[64 * 17];
    __shared__ float  bs[NF];

    int t = threadIdx.x;
    const float4* W4 = (const float4*)W;
#pragma unroll
    for (int i = 0; i < 8; i++) Ws4[t + 128 * i] = W4[t + 128 * i];
    if (t < NF) bs[t] = b[t];

    int rowbase = blockIdx.x * 64;
    const float4* in4 = (mode == 0) ? g_x4 : g_agg4;

#pragma unroll
    for (int i = 0; i < 8; i++) {
        int idx = t + 128 * i;
        int lr = idx >> 4, c = idx & 15;
        int row = rowbase + lr;
        if (row < NN) xs4[lr * 17 + c] = in4[(size_t)row * 16 + c];
    }
    __syncthreads();

    int cg = t & 7;
    int rl = t >> 3;

    unsigned long long a[4][4];
    {
        int cb = cg * 8;
        unsigned long long b0 = pack2(bs[cb + 0], bs[cb + 1]);
        unsigned long long b1 = pack2(bs[cb + 2], bs[cb + 3]);
        unsigned long long b2 = pack2(bs[cb + 4], bs[cb + 5]);
        unsigned long long b3 = pack2(bs[cb + 6], bs[cb + 7]);
#pragma unroll
        for (int i = 0; i < 4; i++) { a[i][0] = b0; a[i][1] = b1; a[i][2] = b2; a[i][3] = b3; }
    }

#pragma unroll 4
    for (int k4 = 0; k4 < 16; k4++) {
        float4 xv[4];
#pragma unroll
        for (int i = 0; i < 4; i++) xv[i] = xs4[(rl + 16 * i) * 17 + k4];
#pragma unroll
        for (int sub = 0; sub < 4; sub++) {
            int k = k4 * 4 + sub;
            const ulonglong2* wp = (const ulonglong2*)(Ws4 + k * 16 + cg * 2);
            ulonglong2 wA = wp[0];
            ulonglong2 wB = wp[1];
#pragma unroll
            for (int i = 0; i < 4; i++) {
                float xk = (sub == 0) ? xv[i].x : (sub == 1) ? xv[i].y : (sub == 2) ? xv[i].z : xv[i].w;
                unsigned long long s = pack2(xk, xk);
                fma2(a[i][0], s, wA.x);
                fma2(a[i][1], s, wA.y);
                fma2(a[i][2], s, wB.x);
                fma2(a[i][3], s, wB.y);
            }
        }
    }

#pragma unroll
    for (int i = 0; i < 4; i++) {
        int row = rowbase + rl + 16 * i;
        if (row >= NN) continue;
        float2 p0 = unpack2(a[i][0]), p1 = unpack2(a[i][1]);
        float2 p2 = unpack2(a[i][2]), p3 = unpack2(a[i][3]);
        float4 r0 = make_float4(p0.x, p0.y, p1.x, p1.y);
        float4 r1 = make_float4(p2.x, p2.y, p3.x, p3.y);
        size_t o = (size_t)row * 16 + cg * 2;
        if (mode == 0) {
            g_h4[o]     = r0;
            g_h4[o + 1] = r1;
            g_agg4[o]     = make_float4(0.f, 0.f, 0.f, 0.f);
            g_agg4[o + 1] = make_float4(0.f, 0.f, 0.f, 0.f);
        } else {
            float4 x0 = g_x4[o], x1 = g_x4[o + 1];
            x0 = make_float4(sp(x0.x + r0.x), sp(x0.y + r0.y), sp(x0.z + r0.z), sp(x0.w + r0.w));
            x1 = make_float4(sp(x1.x + r1.x), sp(x1.y + r1.y), sp(x1.z + r1.z), sp(x1.w + r1.w));
            if (mode == 1) {
                g_x4[o]     = x0;
                g_x4[o + 1] = x1;
            } else {
                int bg = batch[row];
                red_add_v4((float*)(g_gsum4 + (size_t)bg * 16 + cg * 2), x0);
                red_add_v4((float*)(g_gsum4 + (size_t)bg * 16 + cg * 2 + 1), x1);
                if (cg == 0) red_add_f(&g_gcnt[bg], 1.0f);
            }
        }
    }
}

// ---------------- edge kernel: 8 lanes/edge x 2 float4 slots, table-lerp filter ----------------
__global__ void k_edge(const int* __restrict__ src, const int* __restrict__ dst,
                       const float* __restrict__ ea, int conv) {
    int t = threadIdx.x;
    int wid = t >> 5, lane = t & 31;
    int sub = lane >> 3;          // edge within warp (0..3)
    int sl  = lane & 7;           // float4 slots sl and sl+8
    int e = blockIdx.x * 32 + wid * 4 + sub;
    if (e >= NE) return;

    int s = src[e];
    int d = dst[e];
    float dist = ea[e];

    // two independent gather chains (slots sl, sl+8)
    const float4* hp = g_h4 + ((s << 4) + sl);
    float4 h0 = __ldg(hp);
    float4 h1 = __ldg(hp + 8);

    // filter via table lerp
    float bf = dist * ((float)NBIN / 6.0f);
    int bin = (int)bf;
    float fr = bf - (float)bin;
    const float4* row = g_ftab + (conv * NROW + bin) * 16 + sl;
    float4 fa0 = __ldg(row);
    float4 fa1 = __ldg(row + 8);
    float4 fb0 = __ldg(row + 16);
    float4 fb1 = __ldg(row + 24);

    float4 m0, m1;
    m0.x = h0.x * fmaf(fr, fb0.x - fa0.x, fa0.x);
    m0.y = h0.y * fmaf(fr, fb0.y - fa0.y, fa0.y);
    m0.z = h0.z * fmaf(fr, fb0.z - fa0.z, fa0.z);
    m0.w = h0.w * fmaf(fr, fb0.w - fa0.w, fa0.w);
    m1.x = h1.x * fmaf(fr, fb1.x - fa1.x, fa1.x);
    m1.y = h1.y * fmaf(fr, fb1.y - fa1.y, fa1.y);
    m1.z = h1.z * fmaf(fr, fb1.z - fa1.z, fa1.z);
    m1.w = h1.w * fmaf(fr, fb1.w - fa1.w, fa1.w);

    float* ap = (float*)(g_agg4 + ((d << 4) + sl));
    red_add_v4(ap, m0);
    red_add_v4(ap + 32, m1);
}

// ---------------- head: one block (128 threads) per graph ----------------
__global__ void k_head(const float* __restrict__ Wsm, const float* __restrict__ bsm,
                       const float* __restrict__ Wbg1, const float* __restrict__ bbg1,
                       const float* __restrict__ Wbg2, const float* __restrict__ bbg2,
                       const float* __restrict__ Weh1, const float* __restrict__ beh1,
                       const float* __restrict__ Weh2, const float* __restrict__ beh2,
                       float* __restrict__ out) {
    __shared__ float cs[NF];
    __shared__ float c2[2 * NH];
    __shared__ float red[128];

    int g = blockIdx.x, t = threadIdx.x;
    const float* gsum = (const float*)g_gsum4;

    if (t < NF) {
        float cnt = fmaxf(g_gcnt[g], 1.0f);
        cs[t] = gsum[(size_t)g * NF + t] / cnt;
    }
    __syncthreads();

    {
        float acc = bsm[t];
#pragma unroll 8
        for (int k = 0; k < NF; k++) acc += cs[k] * Wsm[k * 128 + t];
        c2[t] = fmaxf(acc, 0.0f);
    }
    __syncthreads();

    float partial;
    if (t < NH) {
        float acc = bbg1[t];
#pragma unroll 8
        for (int k = 0; k < 2 * NH; k++) acc += c2[k] * Wbg1[k * NH + t];
        partial = fmaxf(acc, 0.0f) * Wbg2[t];
    } else {
        int j = t - NH;
        float acc = beh1[j];
#pragma unroll 8
        for (int k = 0; k < 2 * NH; k++) acc += c2[k] * Weh1[k * NH + j];
        partial = fmaxf(acc, 0.0f) * Weh2[j];
    }
    red[t] = partial;
    __syncthreads();

    int base = t & 64;
    int l = t & 63;
#pragma unroll
    for (int s = 32; s > 0; s >>= 1) {
        if (l < s) red[base + l] += red[base + l + s];
        __syncthreads();
    }
    if (t == 0)  out[g]      = red[0]  + bbg2[0];
    if (t == 64) out[NG + g] = red[64] + beh2[0];
}

// ---------------- launch ----------------
extern "C" void kernel_launch(void* const* d_in, const int* in_sizes, int n_in,
                              void* d_out, int out_size) {
    const int*   x_ids = (const int*)d_in[0];
    const int*   eidx  = (const int*)d_in[1];
    const float* ea    = (const float*)d_in[2];
    const int*   batch = (const int*)d_in[3];
    const float* emb   = (const float*)d_in[4];
    const float* W1    = (const float*)d_in[5];
    const float* b1    = (const float*)d_in[6];
    const float* We    = (const float*)d_in[7];
    const float* be    = (const float*)d_in[8];
    const float* W2    = (const float*)d_in[9];
    const float* b2    = (const float*)d_in[10];
    const float* Wsm   = (const float*)d_in[11];
    const float* bsm   = (const float*)d_in[12];
    const float* Wbg1  = (const float*)d_in[13];
    const float* bbg1  = (const float*)d_in[14];
    const float* Wbg2  = (const float*)d_in[15];
    const float* bbg2  = (const float*)d_in[16];
    const float* Weh1  = (const float*)d_in[17];
    const float* beh1  = (const float*)d_in[18];
    const float* Weh2  = (const float*)d_in[19];
    const float* beh2  = (const float*)d_in[20];

    const int* src = eidx;
    const int* dst = eidx + NE;
    float* out = (float*)d_out;

    const int GB = (NN + 63) / 64;

    k_emb_w1<<<NTYPE, 64>>>(emb, W1, b1);
    dim3 tg(NROW, 3);
    k_ftable<<<tg, 64>>>(We, be);
    k_embed0<<<(NN * 16 + 255) / 256, 256>>>(x_ids, (const float4*)emb);

    for (int i = 0; i < 3; i++) {
        if (i > 0)
            k_node_gemm<<<GB, 128>>>(W1 + i * NF * NF, b1 + i * NF, 0, nullptr);
        k_edge<<<NE / 32, 256>>>(src, dst, ea, i);
        k_node_gemm<<<GB, 128>>>(W2 + i * NF * NF, b2 + i * NF, (i == 2) ? 2 : 1, batch);
    }

    k_head<<<NG, 128>>>(Wsm, bsm, Wbg1, bbg1, Wbg2, bbg2, Weh1, beh1, Weh2, beh2, out);
}